// round 2
// baseline (speedup 1.0000x reference)
#include <cuda_runtime.h>
#include <math.h>

#define Bb 4
#define DM 192
#define DI 384
#define Hh 48
#define Ww 48
#define Ll 2304
#define Kk 4
#define Nn 16
#define Rr 12
#define Cc 44   // R + 2N

// ---------------- scratch (static __device__, no allocation) ----------------
__device__ float g_xc  [(size_t)Bb*DI*Ll];        // (B, D, L)  pre-conv x branch
__device__ float g_xcT [(size_t)Bb*Ll*DI];        // (B, L, D)  post conv+gelu
__device__ float g_z1t [(size_t)Bb*Ll*DI];        // (B, L, D)  gelu(z)
__device__ float g_xdbl[(size_t)Bb*Kk*Ll*Cc];     // (B,K,L,44) dts|Bs|Cs
__device__ float g_dlt [(size_t)Bb*Kk*Ll*DI];     // (B,K,L,D)  softplus delta
__device__ float g_ysT [(size_t)Bb*Kk*Ll*DI];     // (B,K,L,D)  scan outputs (+D*u)
__device__ float g_g   [(size_t)Bb*Ll*DI];        // (B, L, D)  gated, pre out_proj

__device__ __forceinline__ float gelu_exact(float x) {
    return 0.5f * x * (1.0f + erff(x * 0.7071067811865476f));
}

__device__ __forceinline__ int map_idx(int k, int l) {
    // gather/scatter index into row-major spatial order for direction k
    if (k == 0) return l;
    if (k == 1) return (l % 48) * 48 + (l / 48);
    if (k == 2) return 2303 - l;
    int m = 2303 - l;
    return (m % 48) * 48 + (m / 48);
}

// ---------------- 1) in_proj GEMM: xz = W(768x192) @ x[b](192x2304) ----------
// epilogue: o<384 -> g_xc (B,D,L); o>=384 -> gelu -> g_z1t (B,L,D)
__global__ void gemm_inproj(const float* __restrict__ W, const float* __restrict__ x) {
    __shared__ float As[16][68];
    __shared__ float Bs[16][68];
    int b = blockIdx.z;
    int mBase = blockIdx.y * 64;
    int nBase = blockIdx.x * 64;
    int tid = threadIdx.x;
    int tm = (tid / 16) * 4, tn = (tid % 16) * 4;
    float acc[4][4];
#pragma unroll
    for (int i = 0; i < 4; i++)
#pragma unroll
        for (int j = 0; j < 4; j++) acc[i][j] = 0.f;

    for (int k0 = 0; k0 < 192; k0 += 16) {
#pragma unroll
        for (int t = 0; t < 4; t++) {
            int i = tid + t * 256;
            int r = i >> 4, c = i & 15;
            As[c][r] = W[(mBase + r) * 192 + k0 + c];
        }
#pragma unroll
        for (int t = 0; t < 4; t++) {
            int i = tid + t * 256;
            int r = i >> 6, c = i & 63;
            Bs[r][c] = x[((size_t)b * 192 + (k0 + r)) * Ll + nBase + c];
        }
        __syncthreads();
#pragma unroll
        for (int kk = 0; kk < 16; kk++) {
            float4 av = *reinterpret_cast<const float4*>(&As[kk][tm]);
            float4 bv = *reinterpret_cast<const float4*>(&Bs[kk][tn]);
            float a[4] = {av.x, av.y, av.z, av.w};
            float bb[4] = {bv.x, bv.y, bv.z, bv.w};
#pragma unroll
            for (int i = 0; i < 4; i++)
#pragma unroll
                for (int j = 0; j < 4; j++) acc[i][j] = fmaf(a[i], bb[j], acc[i][j]);
        }
        __syncthreads();
    }
#pragma unroll
    for (int i = 0; i < 4; i++) {
        int o = mBase + tm + i;
#pragma unroll
        for (int j = 0; j < 4; j++) {
            int l = nBase + tn + j;
            float v = acc[i][j];
            if (o < DI) g_xc[((size_t)b * DI + o) * Ll + l] = v;
            else g_z1t[((size_t)b * Ll + l) * DI + (o - DI)] = gelu_exact(v);
        }
    }
}

// ---------------- 2) depthwise 3x3 conv + bias + gelu, write transposed ------
__global__ void conv_dw(const float* __restrict__ cw, const float* __restrict__ cb) {
    int gid = blockIdx.x * 256 + threadIdx.x;
    if (gid >= Bb * DI * Ll) return;
    int l = gid % Ll;
    int d = (gid / Ll) % DI;
    int b = gid / (Ll * DI);
    int h = l / 48, w = l % 48;
    const float* src = g_xc + ((size_t)b * DI + d) * Ll;
    float acc = cb[d];
#pragma unroll
    for (int dh = 0; dh < 3; dh++) {
        int hh = h + dh - 1;
        if (hh < 0 || hh >= 48) continue;
#pragma unroll
        for (int dw = 0; dw < 3; dw++) {
            int ww = w + dw - 1;
            if (ww < 0 || ww >= 48) continue;
            acc = fmaf(cw[d * 9 + dh * 3 + dw], src[hh * 48 + ww], acc);
        }
    }
    g_xcT[((size_t)b * Ll + l) * DI + d] = gelu_exact(acc);
}

// ---------------- 3) x_dbl = W_k(44x384) @ xs_k : (B,K,L,44) ----------------
__global__ void xdbl_kernel(const float* __restrict__ xpw) {
    __shared__ float xt[24 * 385];
    int lt = blockIdx.x;           // 96 tiles of 24 l
    int bk = blockIdx.y;           // 16
    int b = bk >> 2, k = bk & 3;
    int tid = threadIdx.x;
    for (int i = tid; i < 24 * 384; i += 256) {
        int r = i / 384, c = i % 384;
        int l = lt * 24 + r;
        xt[r * 385 + c] = g_xcT[((size_t)b * Ll + map_idx(k, l)) * DI + c];
    }
    __syncthreads();
    for (int o = tid; o < Cc * 24; o += 256) {
        int c = o / 24, l = o % 24;
        const float* Wk = xpw + ((size_t)k * Cc + c) * DI;
        const float* xr = &xt[l * 385];
        float acc = 0.f;
#pragma unroll 8
        for (int d = 0; d < DI; d++) acc = fmaf(__ldg(&Wk[d]), xr[d], acc);
        g_xdbl[((size_t)bk * Ll + lt * 24 + l) * Cc + c] = acc;
    }
}

// ---------------- 4) delta = softplus(dtw @ dts + bias) : (B,K,L,D) ----------
__global__ void delta_kernel(const float* __restrict__ dtw, const float* __restrict__ dtb) {
    int gid = blockIdx.x * 256 + threadIdx.x;
    if (gid >= Bb * Kk * Ll * DI) return;
    int d = gid % DI;
    int l = (gid / DI) % Ll;
    int bk = gid / (DI * Ll);
    int k = bk & 3;
    const float* xr = g_xdbl + ((size_t)bk * Ll + l) * Cc;
    const float* wr = dtw + ((size_t)k * DI + d) * Rr;
    float acc = dtb[k * DI + d];
#pragma unroll
    for (int r = 0; r < Rr; r++) acc = fmaf(wr[r], xr[r], acc);
    float sp = (acc > 20.f) ? acc : log1pf(__expf(acc));
    g_dlt[gid] = sp;
}

// ---------------- 5) selective scan: 16 lanes per (b,k,d), state n per lane --
__global__ void scan_kernel(const float* __restrict__ Alogs, const float* __restrict__ Ds) {
    __shared__ float sy[16][17];
    int bk = blockIdx.y;
    int b = bk >> 2, k = bk & 3;
    int grp = threadIdx.x >> 4;    // 16 groups => 16 d per block
    int lane = threadIdx.x & 15;   // state index n
    int d = blockIdx.x * 16 + grp;

    float a2 = -__expf(Alogs[((size_t)k * DI + d) * Nn + lane]) * 1.4426950408889634f;
    float Dd = Ds[k * DI + d];
    float h = 0.f, ykeep = 0.f;

    const float* db = g_dlt + (size_t)bk * Ll * DI;
    const float* xd = g_xdbl + (size_t)bk * Ll * Cc;

    for (int l0 = 0; l0 < Ll; l0 += 16) {
#pragma unroll
        for (int j = 0; j < 16; j++) {
            int l = l0 + j;
            int idx = map_idx(k, l);
            float delta = db[(size_t)l * DI + d];
            float u = g_xcT[((size_t)b * Ll + idx) * DI + d];
            float Bn = xd[(size_t)l * Cc + 12 + lane];
            float Cn = xd[(size_t)l * Cc + 28 + lane];
            float dA = exp2f(delta * a2);
            h = fmaf(h, dA, (delta * u) * Bn);
            float y = h * Cn;
            y += __shfl_xor_sync(0xffffffffu, y, 1);
            y += __shfl_xor_sync(0xffffffffu, y, 2);
            y += __shfl_xor_sync(0xffffffffu, y, 4);
            y += __shfl_xor_sync(0xffffffffu, y, 8);
            if (j == lane) ykeep = fmaf(Dd, u, y);
        }
        sy[lane][grp] = ykeep;
        __syncthreads();
        int lrow = threadIdx.x >> 4, dcol = threadIdx.x & 15;
        g_ysT[((size_t)bk * Ll + l0 + lrow) * DI + blockIdx.x * 16 + dcol] = sy[lrow][dcol];
        __syncthreads();
    }
}

// ---------------- 6) cross-merge + LayerNorm + gate -> g_g (B,L,D) ----------
__global__ void merge_ln_gate(const float* __restrict__ lnw, const float* __restrict__ lnb) {
    int bp = blockIdx.x;
    int b = bp / Ll, p = bp % Ll;
    int d = threadIdx.x;
    int t1 = (p % 48) * 48 + (p / 48);
    size_t base = (size_t)b * Kk * Ll;
    float v = g_ysT[(base + 0 * Ll + p) * DI + d]
            + g_ysT[(base + 1 * Ll + t1) * DI + d]
            + g_ysT[(base + 2 * Ll + (2303 - p)) * DI + d]
            + g_ysT[(base + 3 * Ll + (2303 - t1)) * DI + d];

    float s = v, s2 = v * v;
#pragma unroll
    for (int o = 16; o > 0; o >>= 1) {
        s  += __shfl_xor_sync(0xffffffffu, s, o);
        s2 += __shfl_xor_sync(0xffffffffu, s2, o);
    }
    __shared__ float ws[12], ws2[12];
    __shared__ float mu_s, rstd_s;
    int wid = d >> 5, lid = d & 31;
    if (lid == 0) { ws[wid] = s; ws2[wid] = s2; }
    __syncthreads();
    if (d < 32) {
        float a  = (lid < 12) ? ws[lid]  : 0.f;
        float a2 = (lid < 12) ? ws2[lid] : 0.f;
#pragma unroll
        for (int o = 16; o > 0; o >>= 1) {
            a  += __shfl_xor_sync(0xffffffffu, a, o);
            a2 += __shfl_xor_sync(0xffffffffu, a2, o);
        }
        if (lid == 0) {
            float mu = a * (1.0f / DI);
            float var = a2 * (1.0f / DI) - mu * mu;
            mu_s = mu;
            rstd_s = rsqrtf(var + 1e-5f);
        }
    }
    __syncthreads();
    float nv = (v - mu_s) * rstd_s * lnw[d] + lnb[d];
    g_g[((size_t)b * Ll + p) * DI + d] = nv * g_z1t[((size_t)b * Ll + p) * DI + d];
}

// ---------------- 7) out_proj GEMM: out = W2(192x384) @ g^T -----------------
__global__ void gemm_outproj(const float* __restrict__ W2, float* __restrict__ out) {
    __shared__ float As[16][68];
    __shared__ float Bs[16][68];
    int b = blockIdx.z;
    int mBase = blockIdx.y * 64;
    int nBase = blockIdx.x * 64;
    int tid = threadIdx.x;
    int tm = (tid / 16) * 4, tn = (tid % 16) * 4;
    float acc[4][4];
#pragma unroll
    for (int i = 0; i < 4; i++)
#pragma unroll
        for (int j = 0; j < 4; j++) acc[i][j] = 0.f;

    for (int k0 = 0; k0 < DI; k0 += 16) {
#pragma unroll
        for (int t = 0; t < 4; t++) {
            int i = tid + t * 256;
            int r = i >> 4, c = i & 15;
            As[c][r] = W2[(mBase + r) * DI + k0 + c];
        }
#pragma unroll
        for (int t = 0; t < 4; t++) {
            int i = tid + t * 256;
            int c = i >> 4, r = i & 15;   // r fastest: coalesced 64B rows of g
            Bs[r][c] = g_g[((size_t)b * Ll + nBase + c) * DI + k0 + r];
        }
        __syncthreads();
#pragma unroll
        for (int kk = 0; kk < 16; kk++) {
            float4 av = *reinterpret_cast<const float4*>(&As[kk][tm]);
            float4 bv = *reinterpret_cast<const float4*>(&Bs[kk][tn]);
            float a[4] = {av.x, av.y, av.z, av.w};
            float bb[4] = {bv.x, bv.y, bv.z, bv.w};
#pragma unroll
            for (int i = 0; i < 4; i++)
#pragma unroll
                for (int j = 0; j < 4; j++) acc[i][j] = fmaf(a[i], bb[j], acc[i][j]);
        }
        __syncthreads();
    }
#pragma unroll
    for (int i = 0; i < 4; i++) {
        int o = mBase + tm + i;
#pragma unroll
        for (int j = 0; j < 4; j++) {
            int l = nBase + tn + j;
            out[((size_t)b * DM + o) * Ll + l] = acc[i][j];
        }
    }
}

extern "C" void kernel_launch(void* const* d_in, const int* in_sizes, int n_in,
                              void* d_out, int out_size) {
    const float* x     = (const float*)d_in[0];
    const float* inw   = (const float*)d_in[1];
    const float* convw = (const float*)d_in[2];
    const float* convb = (const float*)d_in[3];
    const float* xpw   = (const float*)d_in[4];
    const float* dtw   = (const float*)d_in[5];
    const float* dtb   = (const float*)d_in[6];
    const float* alogs = (const float*)d_in[7];
    const float* ds    = (const float*)d_in[8];
    const float* lnw   = (const float*)d_in[9];
    const float* lnb   = (const float*)d_in[10];
    const float* outw  = (const float*)d_in[11];
    float* out = (float*)d_out;

    gemm_inproj<<<dim3(36, 12, 4), 256>>>(inw, x);
    conv_dw<<<(Bb * DI * Ll + 255) / 256, 256>>>(convw, convb);
    xdbl_kernel<<<dim3(96, 16), 256>>>(xpw);
    delta_kernel<<<(Bb * Kk * Ll * DI + 255) / 256, 256>>>(dtw, dtb);
    scan_kernel<<<dim3(24, 16), 256>>>(alogs, ds);
    merge_ln_gate<<<Bb * Ll, 384>>>(lnw, lnb);
    gemm_outproj<<<dim3(36, 3, 4), 256>>>(outw, out);
}

// round 3
// speedup vs baseline: 1.2559x; 1.2559x over previous
#include <cuda_runtime.h>
#include <math.h>

#define Bb 4
#define DM 192
#define DI 384
#define Hh 48
#define Ww 48
#define Ll 2304
#define Kk 4
#define Nn 16
#define Rr 12
#define Cc 44   // R + 2N

// ---------------- scratch (static __device__, no allocation) ----------------
__device__ float g_xc  [(size_t)Bb*DI*Ll];        // (B, D, L)  pre-conv x branch
__device__ float g_xcT [(size_t)Bb*Ll*DI];        // (B, L, D)  post conv+gelu
__device__ float g_z1t [(size_t)Bb*Ll*DI];        // (B, L, D)  gelu(z)
__device__ float g_xdbl[(size_t)Bb*Kk*Ll*Cc];     // (B,K,L,44) dts|Bs|Cs
__device__ float g_dlt [(size_t)Bb*Kk*Ll*DI];     // (B,K,L,D)  softplus delta
__device__ float g_ysT [(size_t)Bb*Kk*Ll*DI];     // (B,K,L,D)  scan outputs (+D*u)
__device__ float g_g   [(size_t)Bb*Ll*DI];        // (B, L, D)  gated, pre out_proj

__device__ __forceinline__ float gelu_exact(float x) {
    return 0.5f * x * (1.0f + erff(x * 0.7071067811865476f));
}

__device__ __forceinline__ int map_idx(int k, int l) {
    if (k == 0) return l;
    if (k == 1) return (l % 48) * 48 + (l / 48);
    if (k == 2) return 2303 - l;
    int m = 2303 - l;
    return (m % 48) * 48 + (m / 48);
}

// ---------------- 1) in_proj GEMM: xz = W(768x192) @ x[b](192x2304) ----------
__global__ void gemm_inproj(const float* __restrict__ W, const float* __restrict__ x) {
    __shared__ float As[16][68];
    __shared__ float Bs[16][68];
    int b = blockIdx.z;
    int mBase = blockIdx.y * 64;
    int nBase = blockIdx.x * 64;
    int tid = threadIdx.x;
    int tm = (tid / 16) * 4, tn = (tid % 16) * 4;
    float acc[4][4];
#pragma unroll
    for (int i = 0; i < 4; i++)
#pragma unroll
        for (int j = 0; j < 4; j++) acc[i][j] = 0.f;

    for (int k0 = 0; k0 < 192; k0 += 16) {
#pragma unroll
        for (int t = 0; t < 4; t++) {
            int i = tid + t * 256;
            int r = i >> 4, c = i & 15;
            As[c][r] = W[(mBase + r) * 192 + k0 + c];
        }
#pragma unroll
        for (int t = 0; t < 4; t++) {
            int i = tid + t * 256;
            int r = i >> 6, c = i & 63;
            Bs[r][c] = x[((size_t)b * 192 + (k0 + r)) * Ll + nBase + c];
        }
        __syncthreads();
#pragma unroll
        for (int kk = 0; kk < 16; kk++) {
            float4 av = *reinterpret_cast<const float4*>(&As[kk][tm]);
            float4 bv = *reinterpret_cast<const float4*>(&Bs[kk][tn]);
            float a[4] = {av.x, av.y, av.z, av.w};
            float bb[4] = {bv.x, bv.y, bv.z, bv.w};
#pragma unroll
            for (int i = 0; i < 4; i++)
#pragma unroll
                for (int j = 0; j < 4; j++) acc[i][j] = fmaf(a[i], bb[j], acc[i][j]);
        }
        __syncthreads();
    }
#pragma unroll
    for (int i = 0; i < 4; i++) {
        int o = mBase + tm + i;
#pragma unroll
        for (int j = 0; j < 4; j++) {
            int l = nBase + tn + j;
            float v = acc[i][j];
            if (o < DI) g_xc[((size_t)b * DI + o) * Ll + l] = v;
            else g_z1t[((size_t)b * Ll + l) * DI + (o - DI)] = gelu_exact(v);
        }
    }
}

// ---------------- 2) depthwise 3x3 conv + bias + gelu, write transposed ------
__global__ void conv_dw(const float* __restrict__ cw, const float* __restrict__ cb) {
    int gid = blockIdx.x * 256 + threadIdx.x;
    if (gid >= Bb * DI * Ll) return;
    int l = gid % Ll;
    int d = (gid / Ll) % DI;
    int b = gid / (Ll * DI);
    int h = l / 48, w = l % 48;
    const float* src = g_xc + ((size_t)b * DI + d) * Ll;
    float acc = cb[d];
#pragma unroll
    for (int dh = 0; dh < 3; dh++) {
        int hh = h + dh - 1;
        if (hh < 0 || hh >= 48) continue;
#pragma unroll
        for (int dw = 0; dw < 3; dw++) {
            int ww = w + dw - 1;
            if (ww < 0 || ww >= 48) continue;
            acc = fmaf(__ldg(&cw[d * 9 + dh * 3 + dw]), src[hh * 48 + ww], acc);
        }
    }
    g_xcT[((size_t)b * Ll + l) * DI + d] = gelu_exact(acc);
}

// ---------------- 3) x_dbl GEMM: out[bk](44 x 2304) = W_k(44x384) @ xs[bk] ---
// tile: 48(out,c padded) x 64(l), K chunks of 32 in smem; 256 thr, 3x4/thread
__global__ void xdbl_kernel(const float* __restrict__ xpw) {
    __shared__ float Ws[32][49];   // [kd][c]
    __shared__ float Xs[32][68];   // [kd][l], pitch 68 (16B-aligned rows)
    __shared__ int   gidx[64];
    int bk = blockIdx.y;
    int b = bk >> 2, k = bk & 3;
    int l0 = blockIdx.x * 64;
    int tid = threadIdx.x;
    int tc = (tid >> 4) * 3;       // 0,3,...,45
    int tl = (tid & 15) * 4;

    if (tid < 64) gidx[tid] = map_idx(k, l0 + tid);

    float acc[3][4];
#pragma unroll
    for (int i = 0; i < 3; i++)
#pragma unroll
        for (int j = 0; j < 4; j++) acc[i][j] = 0.f;

    // zero-pad weight columns 44..47 once
    if (tid < 128) {
        int kd = tid & 31, c = 44 + (tid >> 5);
        Ws[kd][c] = 0.f;
    }
    __syncthreads();

    for (int k0 = 0; k0 < DI; k0 += 32) {
        // weights: xpw[(k*44+c)*384 + k0+kd]
        for (int i = tid; i < 44 * 32; i += 256) {
            int c = i >> 5, kd = i & 31;
            Ws[kd][c] = xpw[((size_t)(k * Cc + c)) * DI + k0 + kd];
        }
        // x tile: 64 l rows x 32 kd, float4 loads
#pragma unroll
        for (int t = 0; t < 2; t++) {
            int q = tid + t * 256;
            int l = q >> 3, kq = (q & 7) * 4;
            float4 v = *reinterpret_cast<const float4*>(
                &g_xcT[((size_t)b * Ll + gidx[l]) * DI + k0 + kq]);
            Xs[kq][l] = v.x; Xs[kq + 1][l] = v.y;
            Xs[kq + 2][l] = v.z; Xs[kq + 3][l] = v.w;
        }
        __syncthreads();
#pragma unroll
        for (int kd = 0; kd < 32; kd++) {
            float a0 = Ws[kd][tc], a1 = Ws[kd][tc + 1], a2 = Ws[kd][tc + 2];
            float4 bv = *reinterpret_cast<const float4*>(&Xs[kd][tl]);
            float bb[4] = {bv.x, bv.y, bv.z, bv.w};
#pragma unroll
            for (int j = 0; j < 4; j++) {
                acc[0][j] = fmaf(a0, bb[j], acc[0][j]);
                acc[1][j] = fmaf(a1, bb[j], acc[1][j]);
                acc[2][j] = fmaf(a2, bb[j], acc[2][j]);
            }
        }
        __syncthreads();
    }
#pragma unroll
    for (int r = 0; r < 3; r++) {
        int c = tc + r;
        if (c < Cc) {
#pragma unroll
            for (int j = 0; j < 4; j++)
                g_xdbl[((size_t)bk * Ll + l0 + tl + j) * Cc + c] = acc[r][j];
        }
    }
}

// ---------------- 4) delta = softplus(dtw @ dts + bias), weights in regs -----
__global__ void delta_kernel(const float* __restrict__ dtw, const float* __restrict__ dtb) {
    __shared__ float dts[128][12];
    int bk = blockIdx.y;
    int k = bk & 3;
    int l0 = blockIdx.x * 128;
    int d = threadIdx.x;   // 384 threads

    for (int i = threadIdx.x; i < 128 * 12; i += 384) {
        int l = i / 12, r = i % 12;
        dts[l][r] = g_xdbl[((size_t)bk * Ll + l0 + l) * Cc + r];
    }
    float w[12];
    {
        const float4* wp = reinterpret_cast<const float4*>(dtw + ((size_t)k * DI + d) * Rr);
        float4 a = wp[0], bq = wp[1], cq = wp[2];
        w[0]=a.x; w[1]=a.y; w[2]=a.z; w[3]=a.w;
        w[4]=bq.x; w[5]=bq.y; w[6]=bq.z; w[7]=bq.w;
        w[8]=cq.x; w[9]=cq.y; w[10]=cq.z; w[11]=cq.w;
    }
    float bias = dtb[k * DI + d];
    __syncthreads();

    float* outp = &g_dlt[((size_t)bk * Ll + l0) * DI + d];
#pragma unroll 4
    for (int l = 0; l < 128; l++) {
        float acc = bias;
#pragma unroll
        for (int r = 0; r < Rr; r++) acc = fmaf(w[r], dts[l][r], acc);
        float sp = (acc > 20.f) ? acc : log1pf(__expf(acc));
        outp[(size_t)l * DI] = sp;
    }
}

// ---------------- 5) selective scan: 16 lanes per (b,k,d) --------------------
__global__ void scan_kernel(const float* __restrict__ Alogs, const float* __restrict__ Ds) {
    __shared__ float sy[16][17];
    int bk = blockIdx.y;
    int b = bk >> 2, k = bk & 3;
    int grp = threadIdx.x >> 4;
    int lane = threadIdx.x & 15;
    int d = blockIdx.x * 16 + grp;

    float a2 = -__expf(Alogs[((size_t)k * DI + d) * Nn + lane]) * 1.4426950408889634f;
    float Dd = Ds[k * DI + d];
    float h = 0.f, ykeep = 0.f;

    const float* db = g_dlt + (size_t)bk * Ll * DI + d;        // += DI per step
    const float* xb = g_xdbl + (size_t)bk * Ll * Cc + 12 + lane; // += Cc per step
    const float* ub = g_xcT + (size_t)b * Ll * DI + d;         // indexed by map

    int l = 0, t1 = 0, cnt = 0;  // t1 = (l%48)*48 + l/48, maintained incrementally

    for (int l0 = 0; l0 < Ll; l0 += 16) {
#pragma unroll
        for (int j = 0; j < 16; j++) {
            int idx;
            if (k == 0) idx = l;
            else if (k == 1) idx = t1;
            else if (k == 2) idx = 2303 - l;
            else idx = 2303 - t1;

            float delta = db[0];
            float u = ub[(size_t)idx * DI];
            float Bn = xb[0];
            float Cn = xb[16];
            float dA = exp2f(delta * a2);
            h = fmaf(h, dA, (delta * u) * Bn);
            float y = h * Cn;
            y += __shfl_xor_sync(0xffffffffu, y, 1);
            y += __shfl_xor_sync(0xffffffffu, y, 2);
            y += __shfl_xor_sync(0xffffffffu, y, 4);
            y += __shfl_xor_sync(0xffffffffu, y, 8);
            if (j == lane) ykeep = fmaf(Dd, u, y);

            db += DI;
            xb += Cc;
            l++;
            cnt++;
            if (cnt == 48) { cnt = 0; t1 -= 2255; } else t1 += 48;
        }
        sy[lane][grp] = ykeep;
        __syncthreads();
        int lrow = threadIdx.x >> 4, dcol = threadIdx.x & 15;
        g_ysT[((size_t)bk * Ll + l0 + lrow) * DI + blockIdx.x * 16 + dcol] = sy[lrow][dcol];
        __syncthreads();
    }
}

// ---------------- 6) cross-merge + LayerNorm + gate -> g_g (B,L,D) ----------
__global__ void merge_ln_gate(const float* __restrict__ lnw, const float* __restrict__ lnb) {
    int bp = blockIdx.x;
    int b = bp / Ll, p = bp % Ll;
    int d = threadIdx.x;
    int t1 = (p % 48) * 48 + (p / 48);
    size_t base = (size_t)b * Kk * Ll;
    float v = g_ysT[(base + 0 * Ll + p) * DI + d]
            + g_ysT[(base + 1 * Ll + t1) * DI + d]
            + g_ysT[(base + 2 * Ll + (2303 - p)) * DI + d]
            + g_ysT[(base + 3 * Ll + (2303 - t1)) * DI + d];

    float s = v, s2 = v * v;
#pragma unroll
    for (int o = 16; o > 0; o >>= 1) {
        s  += __shfl_xor_sync(0xffffffffu, s, o);
        s2 += __shfl_xor_sync(0xffffffffu, s2, o);
    }
    __shared__ float ws[12], ws2[12];
    __shared__ float mu_s, rstd_s;
    int wid = d >> 5, lid = d & 31;
    if (lid == 0) { ws[wid] = s; ws2[wid] = s2; }
    __syncthreads();
    if (d < 32) {
        float a  = (lid < 12) ? ws[lid]  : 0.f;
        float a2 = (lid < 12) ? ws2[lid] : 0.f;
#pragma unroll
        for (int o = 16; o > 0; o >>= 1) {
            a  += __shfl_xor_sync(0xffffffffu, a, o);
            a2 += __shfl_xor_sync(0xffffffffu, a2, o);
        }
        if (lid == 0) {
            float mu = a * (1.0f / DI);
            float var = a2 * (1.0f / DI) - mu * mu;
            mu_s = mu;
            rstd_s = rsqrtf(var + 1e-5f);
        }
    }
    __syncthreads();
    float nv = (v - mu_s) * rstd_s * lnw[d] + lnb[d];
    g_g[((size_t)b * Ll + p) * DI + d] = nv * g_z1t[((size_t)b * Ll + p) * DI + d];
}

// ---------------- 7) out_proj GEMM: out = W2(192x384) @ g^T -----------------
__global__ void gemm_outproj(const float* __restrict__ W2, float* __restrict__ out) {
    __shared__ float As[16][68];
    __shared__ float Bs[16][68];
    int b = blockIdx.z;
    int mBase = blockIdx.y * 64;
    int nBase = blockIdx.x * 64;
    int tid = threadIdx.x;
    int tm = (tid / 16) * 4, tn = (tid % 16) * 4;
    float acc[4][4];
#pragma unroll
    for (int i = 0; i < 4; i++)
#pragma unroll
        for (int j = 0; j < 4; j++) acc[i][j] = 0.f;

    for (int k0 = 0; k0 < DI; k0 += 16) {
#pragma unroll
        for (int t = 0; t < 4; t++) {
            int i = tid + t * 256;
            int r = i >> 4, c = i & 15;
            As[c][r] = W2[(mBase + r) * DI + k0 + c];
        }
#pragma unroll
        for (int t = 0; t < 4; t++) {
            int i = tid + t * 256;
            int c = i >> 4, r = i & 15;
            Bs[r][c] = g_g[((size_t)b * Ll + nBase + c) * DI + k0 + r];
        }
        __syncthreads();
#pragma unroll
        for (int kk = 0; kk < 16; kk++) {
            float4 av = *reinterpret_cast<const float4*>(&As[kk][tm]);
            float4 bv = *reinterpret_cast<const float4*>(&Bs[kk][tn]);
            float a[4] = {av.x, av.y, av.z, av.w};
            float bb[4] = {bv.x, bv.y, bv.z, bv.w};
#pragma unroll
            for (int i = 0; i < 4; i++)
#pragma unroll
                for (int j = 0; j < 4; j++) acc[i][j] = fmaf(a[i], bb[j], acc[i][j]);
        }
        __syncthreads();
    }
#pragma unroll
    for (int i = 0; i < 4; i++) {
        int o = mBase + tm + i;
#pragma unroll
        for (int j = 0; j < 4; j++) {
            int l = nBase + tn + j;
            out[((size_t)b * DM + o) * Ll + l] = acc[i][j];
        }
    }
}

extern "C" void kernel_launch(void* const* d_in, const int* in_sizes, int n_in,
                              void* d_out, int out_size) {
    const float* x     = (const float*)d_in[0];
    const float* inw   = (const float*)d_in[1];
    const float* convw = (const float*)d_in[2];
    const float* convb = (const float*)d_in[3];
    const float* xpw   = (const float*)d_in[4];
    const float* dtw   = (const float*)d_in[5];
    const float* dtb   = (const float*)d_in[6];
    const float* alogs = (const float*)d_in[7];
    const float* ds    = (const float*)d_in[8];
    const float* lnw   = (const float*)d_in[9];
    const float* lnb   = (const float*)d_in[10];
    const float* outw  = (const float*)d_in[11];
    float* out = (float*)d_out;

    gemm_inproj<<<dim3(36, 12, 4), 256>>>(inw, x);
    conv_dw<<<(Bb * DI * Ll + 255) / 256, 256>>>(convw, convb);
    xdbl_kernel<<<dim3(36, 16), 256>>>(xpw);
    delta_kernel<<<dim3(18, 16), 384>>>(dtw, dtb);
    scan_kernel<<<dim3(24, 16), 256>>>(alogs, ds);
    merge_ln_gate<<<Bb * Ll, 384>>>(lnw, lnb);
    gemm_outproj<<<dim3(36, 3, 4), 256>>>(outw, out);
}